// round 1
// baseline (speedup 1.0000x reference)
#include <cuda_runtime.h>

// ---------------------------------------------------------------------------
// OHEM cross-entropy loss, fused.
//   predict: (8, 19, 512, 512) fp32   target: (8, 512, 512) int32
//   min_kept: scalar int
// Math:
//   logp_t = log_softmax(predict)[target];  prob = exp(logp_t); loss = -logp_t
//   k = min(min_kept, n_valid-1); thr = max(kth_smallest(prob), 0.7)
//   out = mean(loss over valid & prob < thr)
// Fast path: if count(prob < 0.7) > k  =>  thr == 0.7 exactly, answer comes
// from one fused streaming pass. Otherwise flag-gated fallback kernels do a
// histogram select over [0.7, 1].
// ---------------------------------------------------------------------------

namespace {
constexpr int   kC        = 19;
constexpr int   kHWShift  = 18;          // 512*512 = 2^18
constexpr int   kHW       = 1 << kHWShift;
constexpr float kThresh   = 0.7f;
constexpr int   kBins     = 32768;
constexpr int   kMaxBlk   = 16384;
constexpr int   kBlock    = 256;
}

__device__ float        g_psum[kMaxBlk];
__device__ int          g_pcnt[kMaxBlk];
__device__ int          g_pval[kMaxBlk];
__device__ unsigned int g_hist[kBins];
__device__ int          g_flag;   // 1 => fallback path active
__device__ int          g_k;      // order-statistic index
__device__ int          g_c07;    // count(prob < 0.7)
__device__ float        g_thr;    // fallback threshold estimate
__device__ float        g_fsum;
__device__ int          g_fcnt;

// Per-pixel log-softmax + target gather. Fully unrolled; x[] stays in regs,
// dynamic class index handled with predicated selects (no local-mem spill).
__device__ __forceinline__ void pixel_compute(const float* __restrict__ pred,
                                              const int* __restrict__ tgt,
                                              int p, float& prob, float& loss,
                                              bool& valid) {
    int t  = tgt[p];
    valid  = (t != -1);
    int tt = valid ? t : 0;
    const float* base = pred + (((size_t)(p >> kHWShift) * kC) << kHWShift)
                             + (p & (kHW - 1));
    float x[kC];
#pragma unroll
    for (int c = 0; c < kC; c++) x[c] = __ldg(base + ((size_t)c << kHWShift));
    float m = x[0];
#pragma unroll
    for (int c = 1; c < kC; c++) m = fmaxf(m, x[c]);
    float se = 0.f;
#pragma unroll
    for (int c = 0; c < kC; c++) se += expf(x[c] - m);
    float xt = x[0];
#pragma unroll
    for (int c = 1; c < kC; c++) if (c == tt) xt = x[c];
    float logp = xt - m - logf(se);
    prob = expf(logp);
    loss = -logp;
}

// Block reduce of (float, int, int) -> thread 0 of block.
__device__ __forceinline__ void block_reduce3(float& s, int& a, int& b) {
#pragma unroll
    for (int o = 16; o; o >>= 1) {
        s += __shfl_down_sync(0xffffffffu, s, o);
        a += __shfl_down_sync(0xffffffffu, a, o);
        b += __shfl_down_sync(0xffffffffu, b, o);
    }
    __shared__ float sm[kBlock / 32];
    __shared__ int   sa[kBlock / 32], sb[kBlock / 32];
    int lane = threadIdx.x & 31, w = threadIdx.x >> 5;
    if (!lane) { sm[w] = s; sa[w] = a; sb[w] = b; }
    __syncthreads();
    if (w == 0) {
        bool ok = lane < (blockDim.x >> 5);
        s = ok ? sm[lane] : 0.f;
        a = ok ? sa[lane] : 0;
        b = ok ? sb[lane] : 0;
#pragma unroll
        for (int o = 4; o; o >>= 1) {
            s += __shfl_down_sync(0xffu, s, o);
            a += __shfl_down_sync(0xffu, a, o);
            b += __shfl_down_sync(0xffu, b, o);
        }
    }
}

// ---- Kernel 1: fused log-softmax + fast-path accumulation ------------------
__global__ void __launch_bounds__(kBlock)
k_main(const float* __restrict__ pred, const int* __restrict__ tgt, int npix) {
    int p = blockIdx.x * kBlock + threadIdx.x;
    float s = 0.f; int cs = 0, cv = 0;
    if (p < npix) {
        float prob, loss; bool valid;
        pixel_compute(pred, tgt, p, prob, loss, valid);
        cv = valid ? 1 : 0;
        if (valid && prob < kThresh) { s = loss; cs = 1; }
    }
    block_reduce3(s, cs, cv);
    if (threadIdx.x == 0) {
        g_psum[blockIdx.x] = s;
        g_pcnt[blockIdx.x] = cs;
        g_pval[blockIdx.x] = cv;
    }
}

// ---- Kernel 2: single-block decide (and hist zeroing for fallback) ---------
__global__ void __launch_bounds__(kBlock)
k_decide(const int* __restrict__ min_kept_ptr, int nblocks, float* __restrict__ out,
         int default_mk) {
    float s = 0.f; int cs = 0, cv = 0;
    for (int i = threadIdx.x; i < nblocks; i += kBlock) {
        s  += g_psum[i];
        cs += g_pcnt[i];
        cv += g_pval[i];
    }
    block_reduce3(s, cs, cv);
    // zero fallback histogram unconditionally (cheap, needed for replay determinism)
    __syncthreads();
    for (int i = threadIdx.x; i < kBins; i += kBlock) g_hist[i] = 0u;
    if (threadIdx.x == 0) {
        int mk = min_kept_ptr ? *min_kept_ptr : default_mk;
        if (cv <= 0) {                    // no valid pixels: loss = 0
            out[0] = 0.f;
            g_flag = 0;
        } else {
            int idx = min(mk, cv - 1);
            if (idx < 0) idx = 0;
            if (cs > idx) {               // sort_prob[idx] < 0.7 => thr = 0.7
                out[0] = s / fmaxf((float)cs, 1.0f);
                g_flag = 0;
            } else {                      // exact selection needed
                g_flag = 1;
                g_k    = idx;
                g_c07  = cs;
            }
        }
    }
}

// ---- Kernel 3 (gated): histogram of probs in [0.7, 1] ----------------------
__global__ void __launch_bounds__(kBlock)
k_hist(const float* __restrict__ pred, const int* __restrict__ tgt, int npix) {
    if (!g_flag) return;
    const float scale = (float)kBins / (1.0f - kThresh);
    for (int p = blockIdx.x * kBlock + threadIdx.x; p < npix;
         p += gridDim.x * kBlock) {
        float prob, loss; bool valid;
        pixel_compute(pred, tgt, p, prob, loss, valid);
        if (valid && prob >= kThresh) {
            int b = (int)((prob - kThresh) * scale);
            b = min(b, kBins - 1);
            atomicAdd(&g_hist[b], 1u);
        }
    }
}

// ---- Kernel 4 (gated): scan histogram, set threshold, zero accumulators ----
__global__ void k_scan() {
    if (!g_flag) return;
    if (threadIdx.x == 0) {
        long long cum = g_c07;
        int k = g_k;
        int b = 0;
        for (; b < kBins; b++) {
            cum += g_hist[b];
            if (cum > (long long)k) break;
        }
        g_thr  = kThresh + (float)b * ((1.0f - kThresh) / (float)kBins);
        g_fsum = 0.f;
        g_fcnt = 0;
    }
}

// ---- Kernel 5 (gated): re-select with exact(ish) threshold -----------------
__global__ void __launch_bounds__(kBlock)
k_sum(const float* __restrict__ pred, const int* __restrict__ tgt, int npix) {
    if (!g_flag) return;
    float thr = g_thr;
    float s = 0.f; int cs = 0, cv = 0;
    for (int p = blockIdx.x * kBlock + threadIdx.x; p < npix;
         p += gridDim.x * kBlock) {
        float prob, loss; bool valid;
        pixel_compute(pred, tgt, p, prob, loss, valid);
        if (valid && prob < thr) { s += loss; cs++; }
    }
    block_reduce3(s, cs, cv);
    if (threadIdx.x == 0) {
        atomicAdd(&g_fsum, s);
        atomicAdd(&g_fcnt, cs);
    }
}

// ---- Kernel 6 (gated): finalize ------------------------------------------
__global__ void k_final(float* __restrict__ out) {
    if (!g_flag) return;
    out[0] = g_fsum / fmaxf((float)g_fcnt, 1.0f);
}

extern "C" void kernel_launch(void* const* d_in, const int* in_sizes, int n_in,
                              void* d_out, int out_size) {
    const float* pred = (const float*)d_in[0];
    const int*   tgt  = (const int*)d_in[1];
    const int*   mk   = (n_in > 2) ? (const int*)d_in[2] : nullptr;
    int npix    = in_sizes[1];
    int nblocks = (npix + kBlock - 1) / kBlock;
    if (nblocks > kMaxBlk) nblocks = kMaxBlk;   // shapes are fixed; guard only

    k_main  <<<nblocks, kBlock>>>(pred, tgt, npix);
    k_decide<<<1, kBlock>>>(mk, nblocks, (float*)d_out, 131072);
    k_hist  <<<2048, kBlock>>>(pred, tgt, npix);
    k_scan  <<<1, 32>>>();
    k_sum   <<<2048, kBlock>>>(pred, tgt, npix);
    k_final <<<1, 1>>>((float*)d_out);
}

// round 2
// speedup vs baseline: 1.1466x; 1.1466x over previous
#include <cuda_runtime.h>

// ---------------------------------------------------------------------------
// OHEM cross-entropy loss, fused, log-domain fast path.
//   predict: (8, 19, 512, 512) fp32   target: (8, 512, 512) int32
// Fast path: if count(logp < ln0.7) > k  =>  threshold == 0.7 exactly; answer
// from one fused streaming pass (4 pixels/thread, float4 loads, __expf).
// Fallback (flag-gated, small grids): histogram select over prob in [0.7, 1].
// ---------------------------------------------------------------------------

namespace {
constexpr int   kC        = 19;
constexpr int   kHWShift  = 18;          // 512*512 = 2^18
constexpr int   kHW       = 1 << kHWShift;
constexpr float kThresh   = 0.7f;
constexpr float kLogThr   = -0.3566749439387324f;   // ln(0.7)
constexpr int   kBins     = 32768;
constexpr int   kMaxBlk   = 16384;
constexpr int   kBlock    = 256;
}

__device__ float        g_psum[kMaxBlk];
__device__ int          g_pcnt[kMaxBlk];
__device__ int          g_pval[kMaxBlk];
__device__ unsigned int g_hist[kBins];
__device__ int          g_flag;   // 1 => fallback path active
__device__ int          g_k;      // order-statistic index
__device__ int          g_c07;    // count(prob < 0.7)
__device__ float        g_thr;    // fallback threshold estimate
__device__ float        g_fsum;
__device__ int          g_fcnt;

// Scalar per-pixel compute (fallback path only).
__device__ __forceinline__ void pixel_compute(const float* __restrict__ pred,
                                              const int* __restrict__ tgt,
                                              int p, float& prob, float& loss,
                                              bool& valid) {
    int t  = __ldg(tgt + p);
    valid  = (t != -1);
    int tt = valid ? t : 0;
    const float* base = pred + (((size_t)(p >> kHWShift) * kC) << kHWShift)
                             + (p & (kHW - 1));
    float m = -1e30f;
    float x[kC];
#pragma unroll
    for (int c = 0; c < kC; c++) {
        x[c] = __ldg(base + ((size_t)c << kHWShift));
        m = fmaxf(m, x[c]);
    }
    float se = 0.f;
#pragma unroll
    for (int c = 0; c < kC; c++) se += __expf(x[c] - m);
    float xt = __ldg(base + ((size_t)tt << kHWShift));
    float logp = xt - m - __logf(se);
    prob = __expf(logp);
    loss = -logp;
}

// Block reduce of (float, int, int) -> thread 0 of block.
__device__ __forceinline__ void block_reduce3(float& s, int& a, int& b) {
#pragma unroll
    for (int o = 16; o; o >>= 1) {
        s += __shfl_down_sync(0xffffffffu, s, o);
        a += __shfl_down_sync(0xffffffffu, a, o);
        b += __shfl_down_sync(0xffffffffu, b, o);
    }
    __shared__ float sm[kBlock / 32];
    __shared__ int   sa[kBlock / 32], sb[kBlock / 32];
    int lane = threadIdx.x & 31, w = threadIdx.x >> 5;
    if (!lane) { sm[w] = s; sa[w] = a; sb[w] = b; }
    __syncthreads();
    if (w == 0) {
        bool ok = lane < (blockDim.x >> 5);
        s = ok ? sm[lane] : 0.f;
        a = ok ? sa[lane] : 0;
        b = ok ? sb[lane] : 0;
#pragma unroll
        for (int o = 4; o; o >>= 1) {
            s += __shfl_down_sync(0xffu, s, o);
            a += __shfl_down_sync(0xffu, a, o);
            b += __shfl_down_sync(0xffu, b, o);
        }
    }
}

// ---- Kernel 1: fused log-softmax, 4 pixels/thread, float4 loads -----------
__global__ void __launch_bounds__(kBlock)
k_main(const float* __restrict__ pred, const int* __restrict__ tgt, int npix) {
    int idx = blockIdx.x * kBlock + threadIdx.x;
    int p   = idx << 2;
    float s = 0.f; int cs = 0, cv = 0;
    if (p + 3 < npix) {
        const int4 t4 = *(const int4*)(tgt + p);
        const float* base = pred + (((size_t)(p >> kHWShift) * kC) << kHWShift)
                                 + (p & (kHW - 1));
        float4 x[kC];
#pragma unroll
        for (int c = 0; c < kC; c++)
            x[c] = __ldg((const float4*)(base + ((size_t)c << kHWShift)));
        float4 m = x[0];
#pragma unroll
        for (int c = 1; c < kC; c++) {
            m.x = fmaxf(m.x, x[c].x); m.y = fmaxf(m.y, x[c].y);
            m.z = fmaxf(m.z, x[c].z); m.w = fmaxf(m.w, x[c].w);
        }
        float4 se = make_float4(0.f, 0.f, 0.f, 0.f);
#pragma unroll
        for (int c = 0; c < kC; c++) {
            se.x += __expf(x[c].x - m.x); se.y += __expf(x[c].y - m.y);
            se.z += __expf(x[c].z - m.z); se.w += __expf(x[c].w - m.w);
        }
        const int   tv[4] = {t4.x, t4.y, t4.z, t4.w};
        const float mm[4] = {m.x, m.y, m.z, m.w};
        const float ls[4] = {__logf(se.x), __logf(se.y),
                             __logf(se.z), __logf(se.w)};
#pragma unroll
        for (int j = 0; j < 4; j++) {
            bool valid = (tv[j] != -1);
            int  tt    = valid ? tv[j] : 0;
            // L1-hit reload of the target-class logit (line just fetched)
            float xt   = __ldg(base + ((size_t)tt << kHWShift) + j);
            float logp = xt - mm[j] - ls[j];
            cv += valid ? 1 : 0;
            if (valid && logp < kLogThr) { s += -logp; cs++; }
        }
    }
    block_reduce3(s, cs, cv);
    if (threadIdx.x == 0) {
        g_psum[blockIdx.x] = s;
        g_pcnt[blockIdx.x] = cs;
        g_pval[blockIdx.x] = cv;
    }
}

// ---- Kernel 2: single-block decide (and hist zeroing for fallback) ---------
__global__ void __launch_bounds__(kBlock)
k_decide(const int* __restrict__ min_kept_ptr, int nblocks, float* __restrict__ out,
         int default_mk) {
    float s = 0.f; int cs = 0, cv = 0;
    for (int i = threadIdx.x; i < nblocks; i += kBlock) {
        s  += g_psum[i];
        cs += g_pcnt[i];
        cv += g_pval[i];
    }
    block_reduce3(s, cs, cv);
    __syncthreads();
    for (int i = threadIdx.x; i < kBins; i += kBlock) g_hist[i] = 0u;
    if (threadIdx.x == 0) {
        int mk = min_kept_ptr ? *min_kept_ptr : default_mk;
        if (cv <= 0) {                    // no valid pixels: loss = 0
            out[0] = 0.f;
            g_flag = 0;
        } else {
            int idx = min(mk, cv - 1);
            if (idx < 0) idx = 0;
            if (cs > idx) {               // kth prob < 0.7 => thr = 0.7
                out[0] = s / fmaxf((float)cs, 1.0f);
                g_flag = 0;
            } else {                      // exact selection needed
                g_flag = 1;
                g_k    = idx;
                g_c07  = cs;
            }
        }
    }
}

// ---- Kernel 3 (gated): histogram of probs in [0.7, 1] ----------------------
__global__ void __launch_bounds__(kBlock)
k_hist(const float* __restrict__ pred, const int* __restrict__ tgt, int npix) {
    if (!g_flag) return;
    const float scale = (float)kBins / (1.0f - kThresh);
    for (int p = blockIdx.x * kBlock + threadIdx.x; p < npix;
         p += gridDim.x * kBlock) {
        float prob, loss; bool valid;
        pixel_compute(pred, tgt, p, prob, loss, valid);
        if (valid && prob >= kThresh) {
            int b = (int)((prob - kThresh) * scale);
            b = min(b, kBins - 1);
            atomicAdd(&g_hist[b], 1u);
        }
    }
}

// ---- Kernel 4 (gated): scan histogram, set threshold, zero accumulators ----
__global__ void k_scan() {
    if (!g_flag) return;
    if (threadIdx.x == 0) {
        long long cum = g_c07;
        int k = g_k;
        int b = 0;
        for (; b < kBins; b++) {
            cum += g_hist[b];
            if (cum > (long long)k) break;
        }
        g_thr  = kThresh + (float)b * ((1.0f - kThresh) / (float)kBins);
        g_fsum = 0.f;
        g_fcnt = 0;
    }
}

// ---- Kernel 5 (gated): re-select with exact(ish) threshold -----------------
__global__ void __launch_bounds__(kBlock)
k_sum(const float* __restrict__ pred, const int* __restrict__ tgt, int npix) {
    if (!g_flag) return;
    float thr = g_thr;
    float s = 0.f; int cs = 0, cv = 0;
    for (int p = blockIdx.x * kBlock + threadIdx.x; p < npix;
         p += gridDim.x * kBlock) {
        float prob, loss; bool valid;
        pixel_compute(pred, tgt, p, prob, loss, valid);
        if (valid && prob < thr) { s += loss; cs++; }
    }
    block_reduce3(s, cs, cv);
    if (threadIdx.x == 0) {
        atomicAdd(&g_fsum, s);
        atomicAdd(&g_fcnt, cs);
    }
}

// ---- Kernel 6 (gated): finalize ------------------------------------------
__global__ void k_final(float* __restrict__ out) {
    if (!g_flag) return;
    out[0] = g_fsum / fmaxf((float)g_fcnt, 1.0f);
}

extern "C" void kernel_launch(void* const* d_in, const int* in_sizes, int n_in,
                              void* d_out, int out_size) {
    const float* pred = (const float*)d_in[0];
    const int*   tgt  = (const int*)d_in[1];
    const int*   mk   = (n_in > 2) ? (const int*)d_in[2] : nullptr;
    int npix    = in_sizes[1];
    int nquads  = npix >> 2;                         // npix is 2^21
    int nblocks = (nquads + kBlock - 1) / kBlock;    // 2048
    if (nblocks > kMaxBlk) nblocks = kMaxBlk;

    k_main  <<<nblocks, kBlock>>>(pred, tgt, npix);
    k_decide<<<1, kBlock>>>(mk, nblocks, (float*)d_out, 131072);
    k_hist  <<<296, kBlock>>>(pred, tgt, npix);
    k_scan  <<<1, 32>>>();
    k_sum   <<<296, kBlock>>>(pred, tgt, npix);
    k_final <<<1, 1>>>((float*)d_out);
}